// round 8
// baseline (speedup 1.0000x reference)
#include <cuda_runtime.h>
#include <cstdint>

#define BQ 1024
#define TT 365
#define DD 5
#define SS 27
#define HH 256

#define BT   64
#define HC   32
#define GROUPS 16
#define CPG    8
#define NCTA 128
#define NTHR 256
#define KQX 2
#define KQH 64
#define KQC 8            // kq per chunk (8 chunks of 32 h-cols)

__device__ float    g_h[2][BQ][HH];
__device__ unsigned g_flag[GROUPS * CPG * 32];   // per-CTA step counters, 128B apart
__device__ unsigned g_done[GROUPS * 32];

__device__ __forceinline__ unsigned long long pack2(float lo, float hi) {
    unsigned long long r;
    asm("mov.b64 %0, {%1,%2};" : "=l"(r) : "f"(lo), "f"(hi));
    return r;
}
__device__ __forceinline__ void unpack2(unsigned long long v, float &lo, float &hi) {
    asm("mov.b64 {%0,%1}, %2;" : "=f"(lo), "=f"(hi) : "l"(v));
}
__device__ __forceinline__ void ffma2(unsigned long long &d,
                                      unsigned long long a,
                                      unsigned long long b) {
    asm("fma.rn.f32x2 %0, %1, %2, %0;" : "+l"(d) : "l"(a), "l"(b));
}
__device__ __forceinline__ float sigmoidf_(float x) {
    return __fdividef(1.f, 1.f + __expf(-x));
}
__device__ __forceinline__ float tanhf_(float x) {
    float e = __expf(-2.f * fabsf(x));
    return copysignf(__fdividef(1.f - e, 1.f + e), x);
}

__global__ __launch_bounds__(NTHR, 1)
void ealstm_kernel(const float* __restrict__ x_dyn,  const float* __restrict__ x_stat,
                   const float* __restrict__ W_i,    const float* __restrict__ b_i,
                   const float* __restrict__ W_f,    const float* __restrict__ b_f,
                   const float* __restrict__ W_g,    const float* __restrict__ b_g,
                   const float* __restrict__ W_o,    const float* __restrict__ b_o,
                   const float* __restrict__ W_head, const float* __restrict__ b_head,
                   float* __restrict__ out)
{
    const int bi   = blockIdx.x >> 3;
    const int cj   = blockIdx.x & 7;
    const int tid  = threadIdx.x;
    const int col  = tid & 31;
    const int rg   = tid >> 5;
    const int row0 = bi * BT;
    const int colg = cj * HC + col;

    extern __shared__ float4 smem4[];
    float4* hs4  = smem4;                 // [BT][64]   64 KB  (h, step t-1)
    float4* wf4  = hs4  + BT * 64;        // [KQH][HC]  32 KB each
    float4* wg4  = wf4  + KQH * HC;
    float4* wo4  = wg4  + KQH * HC;
    float4* wxf4 = wo4  + KQH * HC;       // [KQX][HC]
    float4* wxg4 = wxf4 + KQX * HC;
    float4* wxo4 = wxg4 + KQX * HC;
    float4* xs4  = wxo4 + KQX * HC;       // [BT][2]
    float*  hsf  = reinterpret_cast<float*>(hs4);

    // ---- one-time: weights -> SMEM (k-major) ----
    for (int e = tid; e < KQH * HC; e += NTHR) {
        const int kq = e >> 5, cc = e & 31;
        const int base = (cj * HC + cc) * (DD + HH) + DD + 4 * kq;
        wf4[kq * HC + cc] = make_float4(W_f[base], W_f[base+1], W_f[base+2], W_f[base+3]);
        wg4[kq * HC + cc] = make_float4(W_g[base], W_g[base+1], W_g[base+2], W_g[base+3]);
        wo4[kq * HC + cc] = make_float4(W_o[base], W_o[base+1], W_o[base+2], W_o[base+3]);
    }
    if (tid < KQX * HC) {
        const int kq = tid >> 5, cc = tid & 31;
        const int base = (cj * HC + cc) * (DD + HH);
        if (kq == 0) {
            wxf4[cc] = make_float4(W_f[base], W_f[base+1], W_f[base+2], W_f[base+3]);
            wxg4[cc] = make_float4(W_g[base], W_g[base+1], W_g[base+2], W_g[base+3]);
            wxo4[cc] = make_float4(W_o[base], W_o[base+1], W_o[base+2], W_o[base+3]);
        } else {
            wxf4[HC + cc] = make_float4(W_f[base+4], 0.f, 0.f, 0.f);
            wxg4[HC + cc] = make_float4(W_g[base+4], 0.f, 0.f, 0.f);
            wxo4[HC + cc] = make_float4(W_o[base+4], 0.f, 0.f, 0.f);
        }
    }
    __syncthreads();

    const float bf_ = __ldg(&b_f[colg]);
    const float bg_ = __ldg(&b_g[colg]);
    const float bo_ = __ldg(&b_o[colg]);

    float ig[8], cst[8];
    {
        const float bi_ = __ldg(&b_i[colg]);
#pragma unroll
        for (int j = 0; j < 8; j++) {
            const int r = row0 + rg * 8 + j;
            float s = bi_;
            for (int ss = 0; ss < SS; ss++)
                s = fmaf(__ldg(&x_stat[r * SS + ss]), __ldg(&W_i[colg * SS + ss]), s);
            ig[j]  = sigmoidf_(s);
            cst[j] = 0.f;
        }
    }

    // ---- recurrence ----
    for (int t = 0; t < TT; t++) {
        // stage x_t
        if (tid < BT) {
            const float* xp = x_dyn + ((size_t)(row0 + tid) * TT + t) * DD;
            const float x0 = __ldg(xp+0), x1 = __ldg(xp+1), x2 = __ldg(xp+2),
                        x3 = __ldg(xp+3), x4 = __ldg(xp+4);
            xs4[tid * 2]     = make_float4(x0, x1, x2, x3);
            xs4[tid * 2 + 1] = make_float4(x4, 0.f, 0.f, 0.f);
        }
        __syncthreads();

        unsigned long long aF[8], aG[8], aO[8];
#pragma unroll
        for (int j = 0; j < 8; j++) {
            aF[j] = pack2(bf_, 0.f);
            aG[j] = pack2(bg_, 0.f);
            aO[j] = pack2(bo_, 0.f);
        }

        // x part
#pragma unroll
        for (int kq = 0; kq < KQX; kq++) {
            const ulonglong2 wfv = *reinterpret_cast<const ulonglong2*>(&wxf4[kq * HC + col]);
            const ulonglong2 wgv = *reinterpret_cast<const ulonglong2*>(&wxg4[kq * HC + col]);
            const ulonglong2 wov = *reinterpret_cast<const ulonglong2*>(&wxo4[kq * HC + col]);
#pragma unroll
            for (int j = 0; j < 8; j++) {
                const ulonglong2 xv =
                    *reinterpret_cast<const ulonglong2*>(&xs4[(rg * 8 + j) * 2 + kq]);
                ffma2(aF[j], xv.x, wfv.x); ffma2(aF[j], xv.y, wfv.y);
                ffma2(aG[j], xv.x, wgv.x); ffma2(aG[j], xv.y, wgv.y);
                ffma2(aO[j], xv.x, wov.x); ffma2(aO[j], xv.y, wov.y);
            }
        }

        if (t > 0) {
            const int rb = (t - 1) & 1;
            // 8 chunks: own first (already in SMEM from our epilogue), then peers
#pragma unroll 1
            for (int i = 0; i < CPG; i++) {
                const int s = (cj + i) & 7;
                if (i > 0) {
                    if (tid == 0) {
                        const volatile unsigned* fp = &g_flag[(bi * CPG + s) * 32];
                        while (*fp < (unsigned)t) __nanosleep(32);
                    }
                    __syncthreads();
                    // stage 64x32 chunk: 512 float4, 2 per thread
                    const float4* src = reinterpret_cast<const float4*>(
                        &g_h[rb][row0][s * HC]);
#pragma unroll
                    for (int q = 0; q < 2; q++) {
                        const int e   = tid * 2 + q;       // 0..511
                        const int r   = e >> 3;            // row
                        const int kk  = e & 7;             // float4 within chunk
                        hs4[r * 64 + s * KQC + kk] = __ldcg(&src[r * 64 + kk]);
                    }
                    __syncthreads();
                }
                // GEMM slab: kq in [s*8, s*8+8)
#pragma unroll
                for (int kk = 0; kk < KQC; kk++) {
                    const int kq = s * KQC + kk;
                    const ulonglong2 wfv = *reinterpret_cast<const ulonglong2*>(&wf4[kq * HC + col]);
                    const ulonglong2 wgv = *reinterpret_cast<const ulonglong2*>(&wg4[kq * HC + col]);
                    const ulonglong2 wov = *reinterpret_cast<const ulonglong2*>(&wo4[kq * HC + col]);
#pragma unroll
                    for (int j = 0; j < 8; j++) {
                        const ulonglong2 hv =
                            *reinterpret_cast<const ulonglong2*>(&hs4[(rg * 8 + j) * 64 + kq]);
                        ffma2(aF[j], hv.x, wfv.x); ffma2(aF[j], hv.y, wfv.y);
                        ffma2(aG[j], hv.x, wgv.x); ffma2(aG[j], hv.y, wgv.y);
                        ffma2(aO[j], hv.x, wov.x); ffma2(aO[j], hv.y, wov.y);
                    }
                }
            }
        }

        // epilogue: all warps done reading hs4 before we overwrite own chunk
        __syncthreads();
        const int wb = t & 1;
#pragma unroll
        for (int j = 0; j < 8; j++) {
            float lo, hi;
            unpack2(aF[j], lo, hi); const float f = sigmoidf_(lo + hi);
            unpack2(aG[j], lo, hi); const float g = tanhf_(lo + hi);
            unpack2(aO[j], lo, hi); const float o = sigmoidf_(lo + hi);
            const float cn = fmaf(f, cst[j], ig[j] * g);
            cst[j] = cn;
            const float hv = o * tanhf_(cn);
            const int r = rg * 8 + j;
            hsf[r * HH + colg] = hv;                       // own chunk -> SMEM (next step)
            __stcg(&g_h[wb][row0 + r][colg], hv);          // publish for peers
        }
        __threadfence();
        __syncthreads();                                   // stores + SMEM writes complete
        if (tid == 0) atomicAdd(&g_flag[(bi * CPG + cj) * 32], 1u);
    }

    // ---- head (cj == 0): wait for whole group, then out = h_T . W_head + b ----
    if (cj == 0) {
        if (tid < CPG) {
            const volatile unsigned* fp = &g_flag[(bi * CPG + tid) * 32];
            while (*fp < (unsigned)TT) __nanosleep(32);
        }
        __syncthreads();
        const int row = tid >> 2, part = tid & 3;
        const int r   = row0 + row;
        const float* hp = &g_h[(TT - 1) & 1][r][0];
        float s = 0.f;
        for (int k = part * 64; k < part * 64 + 64; k++)
            s = fmaf(__ldcg(hp + k), __ldg(&W_head[k]), s);
        s += __shfl_xor_sync(0xffffffffu, s, 1);
        s += __shfl_xor_sync(0xffffffffu, s, 2);
        if (part == 0) out[r] = s + __ldg(&b_head[0]);
    }

    // ---- reset flags for deterministic graph replay ----
    __syncthreads();
    if (tid == 0) {
        __threadfence();
        atomicAdd(&g_done[bi * 32], 1u);
        if (cj == 0) {
            while (atomicAdd(&g_done[bi * 32], 0u) < CPG) __nanosleep(64);
            for (int s = 0; s < CPG; s++)
                atomicExch(&g_flag[(bi * CPG + s) * 32], 0u);
            atomicExch(&g_done[bi * 32], 0u);
        }
    }
}

extern "C" void kernel_launch(void* const* d_in, const int* in_sizes, int n_in,
                              void* d_out, int out_size) {
    (void)in_sizes; (void)n_in; (void)out_size;
    const size_t smem_bytes =
        (size_t)(BT * 64 + 3 * KQH * HC + 3 * KQX * HC + BT * 2) * sizeof(float4);
    cudaFuncSetAttribute(ealstm_kernel,
                         cudaFuncAttributeMaxDynamicSharedMemorySize,
                         (int)smem_bytes);
    ealstm_kernel<<<NCTA, NTHR, smem_bytes>>>(
        (const float*)d_in[0],  (const float*)d_in[1],
        (const float*)d_in[2],  (const float*)d_in[3],
        (const float*)d_in[4],  (const float*)d_in[5],
        (const float*)d_in[6],  (const float*)d_in[7],
        (const float*)d_in[8],  (const float*)d_in[9],
        (const float*)d_in[10], (const float*)d_in[11],
        (float*)d_out);
}

// round 10
// speedup vs baseline: 2.5185x; 2.5185x over previous
#include <cuda_runtime.h>
#include <cuda_fp16.h>
#include <cstdint>

#define BQ 1024
#define TT 365
#define DD 5
#define SS 27
#define HH 256
#define WROW (DD + HH)

#define BT   64          // batch rows per group (MMA M)
#define HC   32          // h-cols per CTA -> N = 96 gate cols
#define NGC  96
#define GROUPS 16
#define CPG    8
#define NCTA 128
#define NTHR 256

#define LO_SCALE 2048.0f
#define LO_INV   (1.0f / 2048.0f)

// SMEM layout (bytes). Rows padded to 528B (33 x 16B) -> conflict-free ldmatrix.
#define ROWB 528
#define OFF_XS  0                      // [64][5] float            1280
#define OFF_P   1280                   // [64][100] float          25600
#define OFF_AHI 26880                  // 64 rows x 528B           33792
#define OFF_ALO 60672
#define OFF_BHI 94464                  // 96 rows x 528B           50688
#define OFF_BLO 145152
#define SMEM_SZ 195840

__device__ __half   g_hhi[2][BQ][HH];
__device__ __half   g_hlo[2][BQ][HH];
__device__ unsigned g_cnt[GROUPS * 32];
__device__ unsigned g_done[GROUPS * 32];

__device__ __forceinline__ uint32_t s2u(const void* p) {
    uint32_t a;
    asm("{ .reg .u64 t; cvta.to.shared.u64 t, %1; cvt.u32.u64 %0, t; }" : "=r"(a) : "l"(p));
    return a;
}
__device__ __forceinline__ float sigmoidf_(float x) {
    return __fdividef(1.f, 1.f + __expf(-x));
}
__device__ __forceinline__ float tanhf_(float x) {
    float e = __expf(-2.f * fabsf(x));
    return copysignf(__fdividef(1.f - e, 1.f + e), x);
}
__device__ __forceinline__ void ldsm4(uint32_t& r0, uint32_t& r1, uint32_t& r2, uint32_t& r3,
                                      uint32_t a) {
    asm volatile("ldmatrix.sync.aligned.m8n8.x4.shared.b16 {%0,%1,%2,%3}, [%4];"
                 : "=r"(r0), "=r"(r1), "=r"(r2), "=r"(r3) : "r"(a));
}
__device__ __forceinline__ void mma16816(float* d, uint32_t a0, uint32_t a1, uint32_t a2,
                                         uint32_t a3, uint32_t b0, uint32_t b1) {
    asm volatile(
        "mma.sync.aligned.m16n8k16.row.col.f32.f16.f16.f32 "
        "{%0,%1,%2,%3}, {%4,%5,%6,%7}, {%8,%9}, {%0,%1,%2,%3};"
        : "+f"(d[0]), "+f"(d[1]), "+f"(d[2]), "+f"(d[3])
        : "r"(a0), "r"(a1), "r"(a2), "r"(a3), "r"(b0), "r"(b1));
}

// Proven R2 group barrier: monotonic counter among the 8 CTAs of a batch group.
__device__ __forceinline__ void group_barrier(int bi, unsigned phase) {
    __threadfence();
    __syncthreads();
    if (threadIdx.x == 0) {
        atomicAdd(&g_cnt[bi * 32], 1u);
        while (atomicAdd(&g_cnt[bi * 32], 0u) < (unsigned)CPG * phase)
            __nanosleep(32);
    }
    __syncthreads();
}

__global__ __launch_bounds__(NTHR, 1)
void ealstm_kernel(const float* __restrict__ x_dyn,  const float* __restrict__ x_stat,
                   const float* __restrict__ W_i,    const float* __restrict__ b_i,
                   const float* __restrict__ W_f,    const float* __restrict__ b_f,
                   const float* __restrict__ W_g,    const float* __restrict__ b_g,
                   const float* __restrict__ W_o,    const float* __restrict__ b_o,
                   const float* __restrict__ W_head, const float* __restrict__ b_head,
                   float* __restrict__ out)
{
    extern __shared__ char smem[];
    const int tid  = threadIdx.x;
    const int wid  = tid >> 5;
    const int lane = tid & 31;
    const int bi   = blockIdx.x >> 3;       // batch group 0..15
    const int cj   = blockIdx.x & 7;        // h-col tile 0..7
    const int row0 = bi * BT;
    const int col0 = cj * HC;

    float* xs = (float*)(smem + OFF_XS);    // [64][5]
    float* P  = (float*)(smem + OFF_P);     // [64][100] (stride 100)

    const uint32_t sAHI = s2u(smem + OFF_AHI);
    const uint32_t sALO = s2u(smem + OFF_ALO);
    const uint32_t sBHI = s2u(smem + OFF_BHI);
    const uint32_t sBLO = s2u(smem + OFF_BLO);

    // ---- one-time: zero A tiles (t=0 GEMM reads zeros) ----
    for (int e = tid; e < (BT * ROWB) / 16; e += NTHR) {
        ((uint4*)(smem + OFF_AHI))[e] = make_uint4(0, 0, 0, 0);
        ((uint4*)(smem + OFF_ALO))[e] = make_uint4(0, 0, 0, 0);
    }
    // ---- one-time: B tiles = recurrent weights, fp16 hi/lo, rows [n][k] padded ----
    for (int e = tid; e < NGC * HH; e += NTHR) {
        const int n = e >> 8, k = e & 255;
        const int gate = n >> 5, col = col0 + (n & 31);
        const float* W = gate == 0 ? W_f : (gate == 1 ? W_g : W_o);
        const float w = __ldg(&W[col * WROW + DD + k]);
        const __half whi = __float2half_rn(w);
        const __half wlo = __float2half_rn((w - __half2float(whi)) * LO_SCALE);
        *(__half*)(smem + OFF_BHI + n * ROWB + k * 2) = whi;
        *(__half*)(smem + OFF_BLO + n * ROWB + k * 2) = wlo;
    }

    // ---- per-thread constants (epilogue mapping: col = lane, rows (tid>>5)*8+j) ----
    const int ecol = lane;
    const int erg  = wid;
    const int colg = col0 + ecol;
    float wxf[DD], wxg[DD], wxo[DD];
#pragma unroll
    for (int d = 0; d < DD; d++) {
        wxf[d] = __ldg(&W_f[colg * WROW + d]);
        wxg[d] = __ldg(&W_g[colg * WROW + d]);
        wxo[d] = __ldg(&W_o[colg * WROW + d]);
    }
    const float bf_ = __ldg(&b_f[colg]);
    const float bg_ = __ldg(&b_g[colg]);
    const float bo_ = __ldg(&b_o[colg]);

    float ig[8], cs[8];
    {
        const float bi_ = __ldg(&b_i[colg]);
#pragma unroll
        for (int j = 0; j < 8; j++) {
            const int r = row0 + erg * 8 + j;
            float s = bi_;
            for (int ss = 0; ss < SS; ss++)
                s = fmaf(__ldg(&x_stat[r * SS + ss]), __ldg(&W_i[colg * SS + ss]), s);
            ig[j] = sigmoidf_(s);
            cs[j] = 0.f;
        }
    }

    // ---- MMA warp geometry: warp = rg(rows 16) x cg(48 cols) ----
    const int rg = wid >> 1;                 // 0..3: rows [rg*16, rg*16+16)
    const int cg = wid & 1;                  // 0..1: cols [cg*48, cg*48+48)
    const int tg  = lane >> 2;               // C-frag row within tile
    const int tig = lane & 3;                // C-frag col pair

    // ldmatrix lane addresses (advance by ks*32 bytes per k16 step)
    const uint32_t aOff = (uint32_t)((rg * 16 + (lane & 15)) * ROWB + (lane >> 4) * 16);
    const uint32_t aHiA = sAHI + aOff;
    const uint32_t aLoA = sALO + aOff;
    uint32_t bHiA[3], bLoA[3];
#pragma unroll
    for (int p = 0; p < 3; p++) {
        const uint32_t bOff =
            (uint32_t)((cg * 48 + p * 16 + ((lane >> 4) * 8) + (lane & 7)) * ROWB +
                       ((lane & 8) ? 16 : 0));
        bHiA[p] = sBHI + bOff;
        bLoA[p] = sBLO + bOff;
    }
    __syncthreads();

    // ---- recurrence ----
    unsigned phase = 0;
    for (int t = 0; t < TT; t++) {
        if (t > 0) {
            phase++;
            group_barrier(bi, phase);
            // stage h(t-1) hi/lo -> padded A tiles (uint4 = 8 halves)
            const int rb = (t - 1) & 1;
            for (int e = tid; e < BT * 32; e += NTHR) {
                const int r = e >> 5, c = e & 31;
                const uint4 vh = __ldcg(((const uint4*)&g_hhi[rb][row0 + r][0]) + c);
                const uint4 vl = __ldcg(((const uint4*)&g_hlo[rb][row0 + r][0]) + c);
                *(uint4*)(smem + OFF_AHI + r * ROWB + c * 16) = vh;
                *(uint4*)(smem + OFF_ALO + r * ROWB + c * 16) = vl;
            }
        }
        // stage x_t
        if (tid < BT) {
            const float* xp = x_dyn + ((size_t)(row0 + tid) * TT + t) * DD;
#pragma unroll
            for (int d = 0; d < DD; d++) xs[tid * DD + d] = __ldg(xp + d);
        }
        __syncthreads();

        // ---- HMMA GEMM: D1 = Ahi*Bhi ; D2 = Ahi*Blo + Alo*Bhi ----
        float d1[6][4], d2[6][4];
#pragma unroll
        for (int q = 0; q < 6; q++)
#pragma unroll
            for (int v = 0; v < 4; v++) { d1[q][v] = 0.f; d2[q][v] = 0.f; }

#pragma unroll
        for (int ks = 0; ks < 16; ks++) {
            const uint32_t kb = (uint32_t)(ks * 32);
            uint32_t ah0, ah1, ah2, ah3, al0, al1, al2, al3;
            ldsm4(ah0, ah1, ah2, ah3, aHiA + kb);
            ldsm4(al0, al1, al2, al3, aLoA + kb);
#pragma unroll
            for (int p = 0; p < 3; p++) {
                uint32_t bh0, bh1, bh2, bh3, bl0, bl1, bl2, bl3;
                ldsm4(bh0, bh1, bh2, bh3, bHiA[p] + kb);
                ldsm4(bl0, bl1, bl2, bl3, bLoA[p] + kb);
                mma16816(d1[p*2+0], ah0, ah1, ah2, ah3, bh0, bh1);
                mma16816(d1[p*2+1], ah0, ah1, ah2, ah3, bh2, bh3);
                mma16816(d2[p*2+0], ah0, ah1, ah2, ah3, bl0, bl1);
                mma16816(d2[p*2+1], ah0, ah1, ah2, ah3, bl2, bl3);
                mma16816(d2[p*2+0], al0, al1, al2, al3, bh0, bh1);
                mma16816(d2[p*2+1], al0, al1, al2, al3, bh2, bh3);
            }
        }

        // P = D1 + D2/2048 -> SMEM (float2 stores, stride 100 floats)
#pragma unroll
        for (int q = 0; q < 6; q++) {
            const int n0 = cg * 48 + (q >> 1) * 16 + (q & 1) * 8;
            const int c2 = (n0 + 2 * tig) >> 1;
            const int ra = rg * 16 + tg, rb2 = ra + 8;
            ((float2*)P)[ra * 50 + c2] =
                make_float2(fmaf(d2[q][0], LO_INV, d1[q][0]), fmaf(d2[q][1], LO_INV, d1[q][1]));
            ((float2*)P)[rb2 * 50 + c2] =
                make_float2(fmaf(d2[q][2], LO_INV, d1[q][2]), fmaf(d2[q][3], LO_INV, d1[q][3]));
        }
        __syncthreads();

        // ---- epilogue: gates + cell update + publish h (hi/lo fp16) ----
        const int wb = t & 1;
#pragma unroll
        for (int j = 0; j < 8; j++) {
            const int row = erg * 8 + j;
            const float x0 = xs[row*DD+0], x1 = xs[row*DD+1], x2 = xs[row*DD+2],
                        x3 = xs[row*DD+3], x4 = xs[row*DD+4];
            float pf = bf_ + P[row * 100 + ecol];
            float pg = bg_ + P[row * 100 + 32 + ecol];
            float po = bo_ + P[row * 100 + 64 + ecol];
            pf = fmaf(x0,wxf[0],pf); pf = fmaf(x1,wxf[1],pf); pf = fmaf(x2,wxf[2],pf);
            pf = fmaf(x3,wxf[3],pf); pf = fmaf(x4,wxf[4],pf);
            pg = fmaf(x0,wxg[0],pg); pg = fmaf(x1,wxg[1],pg); pg = fmaf(x2,wxg[2],pg);
            pg = fmaf(x3,wxg[3],pg); pg = fmaf(x4,wxg[4],pg);
            po = fmaf(x0,wxo[0],po); po = fmaf(x1,wxo[1],po); po = fmaf(x2,wxo[2],po);
            po = fmaf(x3,wxo[3],po); po = fmaf(x4,wxo[4],po);
            const float f = sigmoidf_(pf);
            const float g = tanhf_(pg);
            const float o = sigmoidf_(po);
            const float cn = fmaf(f, cs[j], ig[j] * g);
            cs[j] = cn;
            const float hv = o * tanhf_(cn);
            const __half hhi = __float2half_rn(hv);
            const __half hlo = __float2half_rn((hv - __half2float(hhi)) * LO_SCALE);
            g_hhi[wb][row0 + row][colg] = hhi;
            g_hlo[wb][row0 + row][colg] = hlo;
        }
    }

    // ---- head: out[b] = h_T . W_head + b_head ----
    phase++;
    group_barrier(bi, phase);
    if (cj == 0) {
        const int row = tid >> 2, part = tid & 3;
        const int r = row0 + row;
        const int rb = (TT - 1) & 1;
        float s = 0.f;
        for (int k = part * 64; k < part * 64 + 64; k++) {
            const float hv = __half2float(g_hhi[rb][r][k]) +
                             __half2float(g_hlo[rb][r][k]) * LO_INV;
            s = fmaf(hv, __ldg(&W_head[k]), s);
        }
        s += __shfl_xor_sync(0xffffffffu, s, 1);
        s += __shfl_xor_sync(0xffffffffu, s, 2);
        if (part == 0) out[r] = s + __ldg(&b_head[0]);
    }

    // ---- reset barrier counters for deterministic graph replay ----
    __syncthreads();
    if (tid == 0) {
        __threadfence();
        atomicAdd(&g_done[bi * 32], 1u);
        if (cj == 0) {
            while (atomicAdd(&g_done[bi * 32], 0u) < CPG) __nanosleep(64);
            atomicExch(&g_cnt[bi * 32], 0u);
            atomicExch(&g_done[bi * 32], 0u);
        }
    }
}

extern "C" void kernel_launch(void* const* d_in, const int* in_sizes, int n_in,
                              void* d_out, int out_size) {
    (void)in_sizes; (void)n_in; (void)out_size;
    cudaFuncSetAttribute(ealstm_kernel,
                         cudaFuncAttributeMaxDynamicSharedMemorySize, SMEM_SZ);
    ealstm_kernel<<<NCTA, NTHR, SMEM_SZ>>>(
        (const float*)d_in[0],  (const float*)d_in[1],
        (const float*)d_in[2],  (const float*)d_in[3],
        (const float*)d_in[4],  (const float*)d_in[5],
        (const float*)d_in[6],  (const float*)d_in[7],
        (const float*)d_in[8],  (const float*)d_in[9],
        (const float*)d_in[10], (const float*)d_in[11],
        (float*)d_out);
}